// round 2
// baseline (speedup 1.0000x reference)
#include <cuda_runtime.h>

#define H 64
#define NV_MAX 100000
#define CAP 80

// device scratch (no allocation allowed)
__device__ int g_cnt[NV_MAX];
__device__ int g_slots[(size_t)NV_MAX * CAP];

__global__ void zero_cnt_kernel(int nv) {
    int i = blockIdx.x * blockDim.x + threadIdx.x;
    if (i < nv) g_cnt[i] = 0;
}

// One thread per edge: bucket src id under its dst.
__global__ void fill_kernel(const int* __restrict__ src,
                            const int* __restrict__ dst, int E) {
    int e = blockIdx.x * blockDim.x + threadIdx.x;
    if (e >= E) return;
    int d = dst[e];
    int s = src[e];
    int idx = atomicAdd(&g_cnt[d], 1);
    if (idx < CAP) g_slots[(long)d * CAP + idx] = s;
}

// 256 threads = 4 rows. Per row: 64 threads.
//   gather: thread (gp = h>>4, c = h&15) sums x4[src*16+c] over edges j ≡ gp (mod 4)
//   GEMV:   thread h owns output column h, W row in registers
//   LN:     64-lane shuffle + cross-warp shared reduction
__global__ void __launch_bounds__(256, 2)
fused_kernel(const float4* __restrict__ x4,
             const float* __restrict__ W, const float* __restrict__ b,
             const float* __restrict__ gamma, const float* __restrict__ beta,
             float* __restrict__ out, int nv) {
    const int tid = threadIdx.x;
    const int g = tid >> 6;   // row within group of 4
    const int h = tid & 63;   // column / lane-in-row
    const int c = h & 15;     // float4 chunk
    const int gp = h >> 4;    // edge-parallel group 0..3
    const int wid = tid >> 5;

    // W row h in registers (amortized over the grid-stride loop)
    float Wr[64];
#pragma unroll
    for (int k4 = 0; k4 < 16; k4++) {
        float4 w = reinterpret_cast<const float4*>(W)[h * 16 + k4];
        Wr[4 * k4 + 0] = w.x;
        Wr[4 * k4 + 1] = w.y;
        Wr[4 * k4 + 2] = w.z;
        Wr[4 * k4 + 3] = w.w;
    }
    const float bh = b[h], gh = gamma[h], beh = beta[h];

    __shared__ int s_m[4];
    __shared__ int s_sl[4][CAP];
    __shared__ __align__(16) float s_part[4][4][64];  // [row][gp][col]
    __shared__ __align__(16) float s_S[4][64];
    __shared__ float red1[8], red2[8];

    for (int base = blockIdx.x * 4; base < nv; base += gridDim.x * 4) {
        int row = base + g;
        __syncthreads();  // protect shared reuse across iterations
        if (row < nv && h == 0) s_m[g] = g_cnt[row];
        __syncthreads();
        int dgi = (row < nv) ? s_m[g] : 0;
        int m = min(dgi, CAP);
        if (h < m)      s_sl[g][h]      = g_slots[(long)row * CAP + h];
        if (h + 64 < m) s_sl[g][h + 64] = g_slots[(long)row * CAP + h + 64];
        __syncthreads();

        // gather: sum x rows of this var's sources (all LDG.128, coalesced)
        float4 a0 = make_float4(0.f, 0.f, 0.f, 0.f);
        float4 a1 = make_float4(0.f, 0.f, 0.f, 0.f);
        for (int j = gp; j < m; j += 8) {
            int s0 = s_sl[g][j];
            float4 v0 = x4[(long)s0 * 16 + c];
            a0.x += v0.x; a0.y += v0.y; a0.z += v0.z; a0.w += v0.w;
            if (j + 4 < m) {
                int s1 = s_sl[g][j + 4];
                float4 v1 = x4[(long)s1 * 16 + c];
                a1.x += v1.x; a1.y += v1.y; a1.z += v1.z; a1.w += v1.w;
            }
        }
        float4 a;
        a.x = a0.x + a1.x; a.y = a0.y + a1.y;
        a.z = a0.z + a1.z; a.w = a0.w + a1.w;
        *reinterpret_cast<float4*>(&s_part[g][gp][c * 4]) = a;
        __syncthreads();

        // S[h] = sum over the 4 edge-parallel partials
        float S = s_part[g][0][h] + s_part[g][1][h] + s_part[g][2][h] + s_part[g][3][h];
        s_S[g][h] = S;
        __syncthreads();

        float v = 0.f;
        if (row < nv) {
            const float4* sv = reinterpret_cast<const float4*>(s_S[g]);
            float y = 0.f;
#pragma unroll
            for (int k4 = 0; k4 < 16; k4++) {
                float4 sk = sv[k4];
                y = fmaf(Wr[4 * k4 + 0], sk.x, y);
                y = fmaf(Wr[4 * k4 + 1], sk.y, y);
                y = fmaf(Wr[4 * k4 + 2], sk.z, y);
                y = fmaf(Wr[4 * k4 + 3], sk.w, y);
            }
            float dg = (float)dgi;
            v = (y + dg * bh) / (dg + 1e-6f);
            v = fmaxf(v, 0.f);
        }

        // LayerNorm over 64 lanes (2 warps)
        float s1 = v, s2 = v * v;
#pragma unroll
        for (int off = 16; off > 0; off >>= 1) {
            s1 += __shfl_xor_sync(0xffffffffu, s1, off);
            s2 += __shfl_xor_sync(0xffffffffu, s2, off);
        }
        if ((tid & 31) == 0) { red1[wid] = s1; red2[wid] = s2; }
        __syncthreads();
        float sum = s1 + red1[wid ^ 1];
        float sumsq = s2 + red2[wid ^ 1];

        if (row < nv) {
            float mu = sum * (1.0f / 64.0f);
            float var = sumsq * (1.0f / 64.0f) - mu * mu;
            out[(long)row * H + h] = (v - mu) * rsqrtf(var + 1e-5f) * gh + beh;
        }
    }
}

extern "C" void kernel_launch(void* const* d_in, const int* in_sizes, int n_in,
                              void* d_out, int out_size) {
    const float* x_con = (const float*)d_in[0];
    const int* src = (const int*)d_in[1];
    const int* dst = (const int*)d_in[2];
    // locate W robustly (num_var may or may not be materialized)
    int wi = 3;
    if (in_sizes[3] != H * H) {
        for (int i = 3; i < n_in; i++) {
            if (in_sizes[i] == H * H) { wi = i; break; }
        }
    }
    const float* W = (const float*)d_in[wi];
    const float* b = (const float*)d_in[wi + 1];
    const float* gamma = (const float*)d_in[wi + 2];
    const float* beta = (const float*)d_in[wi + 3];

    int E = in_sizes[1];
    int nv = out_size / H;

    zero_cnt_kernel<<<(nv + 255) / 256, 256>>>(nv);
    fill_kernel<<<(E + 255) / 256, 256>>>(src, dst, E);
    fused_kernel<<<1480, 256>>>((const float4*)x_con, W, b, gamma, beta,
                                (float*)d_out, nv);
}

// round 3
// speedup vs baseline: 1.2842x; 1.2842x over previous
#include <cuda_runtime.h>

#define H 64
#define NV_MAX 100000
#define CAP 80

// device scratch (zero-initialized at module load; fused kernel re-zeros g_cnt)
__device__ int g_cnt[NV_MAX];
__device__ int g_slots[(size_t)NV_MAX * CAP];

__device__ __forceinline__ unsigned long long pk2(float lo, float hi) {
    unsigned long long r;
    asm("mov.b64 %0, {%1, %2};" : "=l"(r) : "f"(lo), "f"(hi));
    return r;
}
__device__ __forceinline__ unsigned long long fma2(unsigned long long a,
                                                   unsigned long long b,
                                                   unsigned long long c) {
    unsigned long long d;
    asm("fma.rn.f32x2 %0, %1, %2, %3;" : "=l"(d) : "l"(a), "l"(b), "l"(c));
    return d;
}
__device__ __forceinline__ unsigned long long add2(unsigned long long a,
                                                   unsigned long long b) {
    unsigned long long d;
    asm("add.rn.f32x2 %0, %1, %2;" : "=l"(d) : "l"(a), "l"(b));
    return d;
}

// One thread per edge: bucket src under dst.
__global__ void fill_kernel(const int* __restrict__ src,
                            const int* __restrict__ dst, int E) {
    int e = blockIdx.x * blockDim.x + threadIdx.x;
    if (e >= E) return;
    int d = dst[e];
    int s = src[e];
    int idx = atomicAdd(&g_cnt[d], 1);
    if (idx < CAP) g_slots[(long)d * CAP + idx] = s;
}

// One WARP per row. No block barriers. 128 threads = 4 independent rows/block.
__global__ void __launch_bounds__(128, 3)
fused_kernel(const float4* __restrict__ x4,
             const float* __restrict__ W, const float* __restrict__ b,
             const float* __restrict__ gamma, const float* __restrict__ beta,
             float* __restrict__ out, int nv) {
    const int lane = threadIdx.x & 31;
    const int w = threadIdx.x >> 5;
    const int c = lane & 15;   // float4 chunk of the row
    const int jg = lane >> 4;  // edge-parallel group (0/1)

    // W rows 2*lane and 2*lane+1 packed into 64 b64 registers (one-time).
    unsigned long long Wp[64];
    {
        const float4* W4 = reinterpret_cast<const float4*>(W);
#pragma unroll
        for (int k4 = 0; k4 < 16; k4++) {
            float4 wa = W4[(2 * lane) * 16 + k4];
            float4 wb = W4[(2 * lane + 1) * 16 + k4];
            Wp[4 * k4 + 0] = pk2(wa.x, wb.x);
            Wp[4 * k4 + 1] = pk2(wa.y, wb.y);
            Wp[4 * k4 + 2] = pk2(wa.z, wb.z);
            Wp[4 * k4 + 3] = pk2(wa.w, wb.w);
        }
    }
    const float2 b2 = reinterpret_cast<const float2*>(b)[lane];
    const float2 g2 = reinterpret_cast<const float2*>(gamma)[lane];
    const float2 e2 = reinterpret_cast<const float2*>(beta)[lane];

    __shared__ int s_sl[4][CAP];
    __shared__ __align__(16) float s_Sd[4][128];  // duplicated S: (S_k,S_k) pairs

    const int nwarps = gridDim.x * 4;
    const int gwarp = blockIdx.x * 4 + w;

    for (int row = gwarp; row < nv; row += nwarps) {
        int dgi = 0;
        if (lane == 0) dgi = g_cnt[row];
        dgi = __shfl_sync(0xffffffffu, dgi, 0);
        int m = min(dgi, CAP);
        if (lane < m)      s_sl[w][lane]      = g_slots[(long)row * CAP + lane];
        if (lane + 32 < m) s_sl[w][lane + 32] = g_slots[(long)row * CAP + lane + 32];
        if (lane + 64 < m) s_sl[w][lane + 64] = g_slots[(long)row * CAP + lane + 64];
        if (lane == 0) g_cnt[row] = 0;  // restore for next kernel_launch call
        __syncwarp();

        // gather: this thread sums chunk c over edges j ≡ jg (mod 2), 2 in flight
        float4 a0 = make_float4(0.f, 0.f, 0.f, 0.f);
        float4 a1 = make_float4(0.f, 0.f, 0.f, 0.f);
        int j = jg;
        for (; j + 2 < m; j += 4) {
            int s0 = s_sl[w][j];
            int s1 = s_sl[w][j + 2];
            float4 v0 = x4[(long)s0 * 16 + c];
            float4 v1 = x4[(long)s1 * 16 + c];
            a0.x += v0.x; a0.y += v0.y; a0.z += v0.z; a0.w += v0.w;
            a1.x += v1.x; a1.y += v1.y; a1.z += v1.z; a1.w += v1.w;
        }
        if (j < m) {
            float4 v0 = x4[(long)s_sl[w][j] * 16 + c];
            a0.x += v0.x; a0.y += v0.y; a0.z += v0.z; a0.w += v0.w;
        }
        a0.x += a1.x; a0.y += a1.y; a0.z += a1.z; a0.w += a1.w;
        // fold the two edge-groups (lane ^ 16)
        a0.x += __shfl_xor_sync(0xffffffffu, a0.x, 16);
        a0.y += __shfl_xor_sync(0xffffffffu, a0.y, 16);
        a0.z += __shfl_xor_sync(0xffffffffu, a0.z, 16);
        a0.w += __shfl_xor_sync(0xffffffffu, a0.w, 16);
        // lanes 0..15 hold S[4c..4c+3]; store duplicated (S_k,S_k) pairs
        if (lane < 16) {
            float4* p = reinterpret_cast<float4*>(&s_Sd[w][8 * lane]);
            p[0] = make_float4(a0.x, a0.x, a0.y, a0.y);
            p[1] = make_float4(a0.z, a0.z, a0.w, a0.w);
        }
        __syncwarp();

        // GEMV: columns h0=2*lane, h1=2*lane+1 via packed f32x2 FMA
        const ulonglong2* sd = reinterpret_cast<const ulonglong2*>(s_Sd[w]);
        unsigned long long yA = 0ull, yB = 0ull;
#pragma unroll
        for (int kk = 0; kk < 32; kk++) {
            ulonglong2 ss = sd[kk];  // broadcast LDS.128: (S_2kk x2, S_2kk+1 x2)
            yA = fma2(Wp[2 * kk], ss.x, yA);
            yB = fma2(Wp[2 * kk + 1], ss.y, yB);
        }
        unsigned long long yP = add2(yA, yB);
        float y0, y1;
        asm("mov.b64 {%0, %1}, %2;" : "=f"(y0), "=f"(y1) : "l"(yP));

        float dg = (float)dgi;
        float inv = 1.0f / (dg + 1e-6f);
        float v0 = fmaxf((y0 + dg * b2.x) * inv, 0.f);
        float v1 = fmaxf((y1 + dg * b2.y) * inv, 0.f);

        // LayerNorm across the 64 columns (2 per lane)
        float s1 = v0 + v1;
        float s2 = v0 * v0 + v1 * v1;
#pragma unroll
        for (int off = 16; off > 0; off >>= 1) {
            s1 += __shfl_xor_sync(0xffffffffu, s1, off);
            s2 += __shfl_xor_sync(0xffffffffu, s2, off);
        }
        float mu = s1 * (1.0f / 64.0f);
        float var = s2 * (1.0f / 64.0f) - mu * mu;
        float r = rsqrtf(var + 1e-5f);
        float2 o;
        o.x = (v0 - mu) * r * g2.x + e2.x;
        o.y = (v1 - mu) * r * g2.y + e2.y;
        reinterpret_cast<float2*>(out)[(long)row * 32 + lane] = o;
    }
}

extern "C" void kernel_launch(void* const* d_in, const int* in_sizes, int n_in,
                              void* d_out, int out_size) {
    const float* x_con = (const float*)d_in[0];
    const int* src = (const int*)d_in[1];
    const int* dst = (const int*)d_in[2];
    int wi = 3;
    if (in_sizes[3] != H * H) {
        for (int i = 3; i < n_in; i++)
            if (in_sizes[i] == H * H) { wi = i; break; }
    }
    const float* W = (const float*)d_in[wi];
    const float* b = (const float*)d_in[wi + 1];
    const float* gamma = (const float*)d_in[wi + 2];
    const float* beta = (const float*)d_in[wi + 3];

    int E = in_sizes[1];
    int nv = out_size / H;

    fill_kernel<<<(E + 255) / 256, 256>>>(src, dst, E);
    fused_kernel<<<444, 128>>>((const float4*)x_con, W, b, gamma, beta,
                               (float*)d_out, nv);
}

// round 4
// speedup vs baseline: 1.6241x; 1.2647x over previous
#include <cuda_runtime.h>

#define H 64
#define NV_MAX 100000
#define CAP 80

// device scratch (zero-initialized at load; fused kernel re-zeros g_cnt each call)
__device__ int g_cnt[NV_MAX];
__device__ int g_slots[(size_t)NV_MAX * CAP];

__device__ __forceinline__ unsigned long long pk2(float lo, float hi) {
    unsigned long long r;
    asm("mov.b64 %0, {%1, %2};" : "=l"(r) : "f"(lo), "f"(hi));
    return r;
}
__device__ __forceinline__ unsigned long long fma2(unsigned long long a,
                                                   unsigned long long b,
                                                   unsigned long long c) {
    unsigned long long d;
    asm("fma.rn.f32x2 %0, %1, %2, %3;" : "=l"(d) : "l"(a), "l"(b), "l"(c));
    return d;
}
__device__ __forceinline__ unsigned long long add2(unsigned long long a,
                                                   unsigned long long b) {
    unsigned long long d;
    asm("add.rn.f32x2 %0, %1, %2;" : "=l"(d) : "l"(a), "l"(b));
    return d;
}

__global__ void fill_kernel(const int* __restrict__ src,
                            const int* __restrict__ dst, int E) {
    int e = blockIdx.x * blockDim.x + threadIdx.x;
    if (e >= E) return;
    int d = dst[e];
    int s = src[e];
    int idx = atomicAdd(&g_cnt[d], 1);
    if (idx < CAP) g_slots[(long)d * CAP + idx] = s;
}

// 256 threads = 8 warps = 8 rows per pass.
//  gather:  warp w gathers row base+w (lanes: 16 chunks x 2 edge groups)
//  GEMV:    warp w computes k in [8w, 8w+8) for ALL 8 rows (Wp = 8 b64 regs)
//  epilogue: warp w sums the 8 k-partials for its row, deg/ReLU/LN/store
__global__ void __launch_bounds__(256, 3)
fused_kernel(const float4* __restrict__ x4,
             const float* __restrict__ W, const float* __restrict__ b,
             const float* __restrict__ gamma, const float* __restrict__ beta,
             float* __restrict__ out, int nv) {
    const int lane = threadIdx.x & 31;
    const int w = threadIdx.x >> 5;   // warp id 0..7 (= k-eighth, = row slot)
    const int c = lane & 15;          // float4 chunk for gather
    const int jg = lane >> 4;         // edge-parallel group

    // W for columns (2*lane, 2*lane+1), k in [8w, 8w+8): 8 packed b64 regs.
    unsigned long long Wp[8];
#pragma unroll
    for (int kq = 0; kq < 8; kq++) {
        int k = 8 * w + kq;
        Wp[kq] = pk2(W[(2 * lane) * H + k], W[(2 * lane + 1) * H + k]);
    }
    const float2 b2 = reinterpret_cast<const float2*>(b)[lane];
    const float2 g2 = reinterpret_cast<const float2*>(gamma)[lane];
    const float2 e2 = reinterpret_cast<const float2*>(beta)[lane];

    __shared__ int s_sl[8][CAP];
    __shared__ __align__(16) float s_Sd[8][128];          // duplicated S pairs
    __shared__ unsigned long long s_part[8][8][32];       // [row][kwarp][colpair]

    for (int base = blockIdx.x * 8; base < nv; base += gridDim.x * 8) {
        const int row = base + w;
        int dgi = 0;

        if (row < nv) {
            if (lane == 0) dgi = g_cnt[row];
            dgi = __shfl_sync(0xffffffffu, dgi, 0);
            int m = min(dgi, CAP);
            if (lane < m)      s_sl[w][lane]      = g_slots[(long)row * CAP + lane];
            if (lane + 32 < m) s_sl[w][lane + 32] = g_slots[(long)row * CAP + lane + 32];
            if (lane + 64 < m) s_sl[w][lane + 64] = g_slots[(long)row * CAP + lane + 64];
            if (lane == 0) g_cnt[row] = 0;   // restore for next launch call
            __syncwarp();

            // gather: sum chunk c over edges j ≡ jg (mod 2), 2 loads in flight
            float4 a0 = make_float4(0.f, 0.f, 0.f, 0.f);
            float4 a1 = make_float4(0.f, 0.f, 0.f, 0.f);
            int j = jg;
            for (; j + 2 < m; j += 4) {
                int s0 = s_sl[w][j];
                int s1 = s_sl[w][j + 2];
                float4 v0 = x4[(long)s0 * 16 + c];
                float4 v1 = x4[(long)s1 * 16 + c];
                a0.x += v0.x; a0.y += v0.y; a0.z += v0.z; a0.w += v0.w;
                a1.x += v1.x; a1.y += v1.y; a1.z += v1.z; a1.w += v1.w;
            }
            if (j < m) {
                float4 v0 = x4[(long)s_sl[w][j] * 16 + c];
                a0.x += v0.x; a0.y += v0.y; a0.z += v0.z; a0.w += v0.w;
            }
            a0.x += a1.x; a0.y += a1.y; a0.z += a1.z; a0.w += a1.w;
            a0.x += __shfl_xor_sync(0xffffffffu, a0.x, 16);
            a0.y += __shfl_xor_sync(0xffffffffu, a0.y, 16);
            a0.z += __shfl_xor_sync(0xffffffffu, a0.z, 16);
            a0.w += __shfl_xor_sync(0xffffffffu, a0.w, 16);
            if (lane < 16) {   // duplicated (S_k, S_k) pairs
                float4* p = reinterpret_cast<float4*>(&s_Sd[w][8 * lane]);
                p[0] = make_float4(a0.x, a0.x, a0.y, a0.y);
                p[1] = make_float4(a0.z, a0.z, a0.w, a0.w);
            }
        } else {
            if (lane < 16) {
                float4* p = reinterpret_cast<float4*>(&s_Sd[w][8 * lane]);
                p[0] = make_float4(0.f, 0.f, 0.f, 0.f);
                p[1] = make_float4(0.f, 0.f, 0.f, 0.f);
            }
        }
        __syncthreads();

        // partial GEMV: this warp's k-eighth for all 8 rows
#pragma unroll
        for (int r = 0; r < 8; r++) {
            const ulonglong2* sd =
                reinterpret_cast<const ulonglong2*>(&s_Sd[r][16 * w]);
            unsigned long long yA = 0ull, yB = 0ull;
#pragma unroll
            for (int t = 0; t < 4; t++) {
                ulonglong2 ss = sd[t];   // broadcast LDS.128
                yA = fma2(Wp[2 * t],     ss.x, yA);
                yB = fma2(Wp[2 * t + 1], ss.y, yB);
            }
            s_part[r][w][lane] = add2(yA, yB);
        }
        __syncthreads();

        // epilogue for this warp's row
        if (row < nv) {
            unsigned long long p0 = add2(s_part[w][0][lane], s_part[w][1][lane]);
            unsigned long long p1 = add2(s_part[w][2][lane], s_part[w][3][lane]);
            unsigned long long p2 = add2(s_part[w][4][lane], s_part[w][5][lane]);
            unsigned long long p3 = add2(s_part[w][6][lane], s_part[w][7][lane]);
            unsigned long long yP = add2(add2(p0, p1), add2(p2, p3));
            float y0, y1;
            asm("mov.b64 {%0, %1}, %2;" : "=f"(y0), "=f"(y1) : "l"(yP));

            float dg = (float)dgi;
            float inv = 1.0f / (dg + 1e-6f);
            float v0 = fmaxf((y0 + dg * b2.x) * inv, 0.f);
            float v1 = fmaxf((y1 + dg * b2.y) * inv, 0.f);

            float s1 = v0 + v1;
            float s2 = v0 * v0 + v1 * v1;
#pragma unroll
            for (int off = 16; off > 0; off >>= 1) {
                s1 += __shfl_xor_sync(0xffffffffu, s1, off);
                s2 += __shfl_xor_sync(0xffffffffu, s2, off);
            }
            float mu = s1 * (1.0f / 64.0f);
            float var = s2 * (1.0f / 64.0f) - mu * mu;
            float r = rsqrtf(var + 1e-5f);
            float2 o;
            o.x = (v0 - mu) * r * g2.x + e2.x;
            o.y = (v1 - mu) * r * g2.y + e2.y;
            reinterpret_cast<float2*>(out)[(long)row * 32 + lane] = o;
        }
    }
}

extern "C" void kernel_launch(void* const* d_in, const int* in_sizes, int n_in,
                              void* d_out, int out_size) {
    const float* x_con = (const float*)d_in[0];
    const int* src = (const int*)d_in[1];
    const int* dst = (const int*)d_in[2];
    int wi = 3;
    if (in_sizes[3] != H * H) {
        for (int i = 3; i < n_in; i++)
            if (in_sizes[i] == H * H) { wi = i; break; }
    }
    const float* W = (const float*)d_in[wi];
    const float* b = (const float*)d_in[wi + 1];
    const float* gamma = (const float*)d_in[wi + 2];
    const float* beta = (const float*)d_in[wi + 3];

    int E = in_sizes[1];
    int nv = out_size / H;

    fill_kernel<<<(E + 255) / 256, 256>>>(src, dst, E);
    fused_kernel<<<444, 256>>>((const float4*)x_con, W, b, gamma, beta,
                               (float*)d_out, nv);
}